// round 5
// baseline (speedup 1.0000x reference)
#include <cuda_runtime.h>
#include <math_constants.h>

#define BB 16
#define CC 256
#define RR 64
#define HW 16384
#define HW4 (HW / 4)                 // 4096 float4 per plane per component
#define HALF4 (HW4 / 2)              // 2048 float4 per half-plane
#define NPLANE (BB * CC)
#define BATCH_F4 (CC * HW4)          // 1048576 float4 per batch per component
#define NEG_SLOPE 0.01f

#define NTHR 256
#define POOLB 512                    // pool blocks: one half-plane each
#define GATEBID POOLB                // bid 512: gate spinner block
#define APPLY0 (POOLB + 1)           // first apply block
#define NAPPLY 2048                  // 2048 apply blocks x 512 float4 = BATCH_F4
#define FGRID (APPLY0 + NAPPLY)      // 2561
#define APPLY_CHUNK 512              // float4 per apply block (1/8 plane -> single channel)

// ---- scratch (__device__ globals; allocation-free rule) ----
__device__ float g_hsr[BB][POOLB], g_hsi[BB][POOLB];   // half-plane sums
__device__ float g_hmr[BB][POOLB], g_hmi[BB][POOLB];   // half-plane maxes
__device__ float g_gr[NPLANE], g_gi[NPLANE];           // gates
__device__ int   g_cnt[BB];

__global__ void reset_kernel() {
    if (threadIdx.x < BB) g_cnt[threadIdx.x] = 0;
}

__global__ __launch_bounds__(NTHR) void F_kernel(
    int b,
    const float* __restrict__ xr, const float* __restrict__ xi,
    float* __restrict__ out,
    const float* __restrict__ w1r, const float* __restrict__ w1i,
    const float* __restrict__ b1r, const float* __restrict__ b1i,
    const float* __restrict__ w2r, const float* __restrict__ w2i,
    const float* __restrict__ b2r, const float* __restrict__ b2i)
{
    const int bid = blockIdx.x;
    const int tid = threadIdx.x;

    // ================= APPLY batch b-1 (no intra-launch dependency) =========
    if (bid >= APPLY0) {
        const int ab = b - 1;
        if (ab < 0) return;
        const int blk = bid - APPLY0;                 // 0..2047
        const int c = blk >> 3;                       // one channel per block
        const float gr = __ldg(&g_gr[ab * CC + c]);
        const float gi = __ldg(&g_gi[ab * CC + c]);

        const size_t base = (size_t)ab * BATCH_F4 + (size_t)blk * APPLY_CHUNK;
        const float4* pr = reinterpret_cast<const float4*>(xr) + base;
        const float4* pi = reinterpret_cast<const float4*>(xi) + base;
        float4* por = reinterpret_cast<float4*>(out) + base;
        float4* poi = reinterpret_cast<float4*>(out) + (size_t)NPLANE * HW4 + base;

#pragma unroll
        for (int k = 0; k < APPLY_CHUNK / NTHR; k++) {   // 2 iters
            const int i = k * NTHR + tid;
            const float4 a = __ldcs(pr + i);   // expect L2 hit; evict-first after
            const float4 bv = __ldcs(pi + i);
            float4 r, m;
            r.x = fmaf(a.x, gr, -bv.x * gi);
            r.y = fmaf(a.y, gr, -bv.y * gi);
            r.z = fmaf(a.z, gr, -bv.z * gi);
            r.w = fmaf(a.w, gr, -bv.w * gi);
            m.x = fmaf(a.x, gi, bv.x * gr);
            m.y = fmaf(a.y, gi, bv.y * gr);
            m.z = fmaf(a.z, gi, bv.z * gr);
            m.w = fmaf(a.w, gi, bv.w * gr);
            __stcs(por + i, r);                // streaming: don't pollute L2
            __stcs(poi + i, m);
        }
        return;
    }

    // ================= POOL batch b (half-plane per block) ===================
    if (bid < POOLB) {
        if (b >= BB) return;
        const int plane = b * CC + (bid >> 1);
        const size_t base = (size_t)plane * HW4 + (size_t)(bid & 1) * HALF4;
        const float4* pr = reinterpret_cast<const float4*>(xr) + base;
        const float4* pi = reinterpret_cast<const float4*>(xi) + base;

        float sr = 0.f, si = 0.f;
        float mr = -CUDART_INF_F, mi = -CUDART_INF_F;
#pragma unroll
        for (int k = 0; k < HALF4 / NTHR; k++) {          // 8 iters
            const int i = k * NTHR + tid;
            const float4 a = pr[i];                       // cache normally (L2)
            const float4 bv = pi[i];
            sr += (a.x + a.y) + (a.z + a.w);
            si += (bv.x + bv.y) + (bv.z + bv.w);
            mr = fmaxf(mr, fmaxf(fmaxf(a.x, a.y), fmaxf(a.z, a.w)));
            mi = fmaxf(mi, fmaxf(fmaxf(bv.x, bv.y), fmaxf(bv.z, bv.w)));
        }
#pragma unroll
        for (int o = 16; o > 0; o >>= 1) {
            sr += __shfl_down_sync(0xFFFFFFFFu, sr, o);
            si += __shfl_down_sync(0xFFFFFFFFu, si, o);
            mr = fmaxf(mr, __shfl_down_sync(0xFFFFFFFFu, mr, o));
            mi = fmaxf(mi, __shfl_down_sync(0xFFFFFFFFu, mi, o));
        }
        __shared__ float red_sr[8], red_si[8], red_mr[8], red_mi[8];
        const int wid = tid >> 5, lid = tid & 31;
        if (lid == 0) { red_sr[wid] = sr; red_si[wid] = si; red_mr[wid] = mr; red_mi[wid] = mi; }
        __syncthreads();
        if (tid == 0) {
            float tsr = red_sr[0], tsi = red_si[0], tmr = red_mr[0], tmi = red_mi[0];
#pragma unroll
            for (int w = 1; w < 8; w++) {
                tsr += red_sr[w]; tsi += red_si[w];
                tmr = fmaxf(tmr, red_mr[w]); tmi = fmaxf(tmi, red_mi[w]);
            }
            g_hsr[b][bid] = tsr; g_hsi[b][bid] = tsi;
            g_hmr[b][bid] = tmr; g_hmi[b][bid] = tmi;
            __threadfence();                              // release partials
            atomicAdd(&g_cnt[b], 1);
        }
        return;
    }

    // ================= GATE batch b (single spinner block, bid == 512) =======
    {
        if (b >= BB) return;
        if (tid == 0) {
            while (atomicAdd(&g_cnt[b], 0) < POOLB) __nanosleep(64);
        }
        __syncthreads();
        __threadfence();                                   // acquire partials

        __shared__ float s_in[4][CC];
        __shared__ float s_h[4][RR];
        {   // combine half-plane partials -> pooled per-channel values
            const int h0 = 2 * tid, h1 = 2 * tid + 1;
            s_in[0][tid] = (g_hsr[b][h0] + g_hsr[b][h1]) * (1.0f / HW);
            s_in[1][tid] = (g_hsi[b][h0] + g_hsi[b][h1]) * (1.0f / HW);
            s_in[2][tid] = fmaxf(g_hmr[b][h0], g_hmr[b][h1]);
            s_in[3][tid] = fmaxf(g_hmi[b][h0], g_hmi[b][h1]);
        }
        __syncthreads();

        if (tid < 2 * RR) {   // layer 1 + complex LeakyReLU: {avg,max} x 64
            const int which = tid >> 6;
            const int r = tid & (RR - 1);
            const float* zr = s_in[2 * which];
            const float* zi = s_in[2 * which + 1];
            float yr = b1r[r], yi = b1i[r];
#pragma unroll 8
            for (int c = 0; c < CC; c++) {
                const float wr = w1r[r * CC + c];
                const float wi = w1i[r * CC + c];
                const float zrc = zr[c], zic = zi[c];
                yr = fmaf(zrc, wr, fmaf(-zic, wi, yr));
                yi = fmaf(zrc, wi, fmaf(zic, wr, yi));
            }
            yr = (yr > 0.f) ? yr : NEG_SLOPE * yr;
            yi = (yi > 0.f) ? yi : NEG_SLOPE * yi;
            s_h[2 * which][r] = yr;
            s_h[2 * which + 1][r] = yi;
        }
        __syncthreads();

        {   // layer 2 both branches + sigmoid; thread = output channel
            float ar = b2r[tid], ai = b2i[tid];
            float mr2 = ar, mi2 = ai;
#pragma unroll 8
            for (int j = 0; j < RR; j++) {
                const float wr = w2r[tid * RR + j];
                const float wi = w2i[tid * RR + j];
                const float har = s_h[0][j], hai = s_h[1][j];
                const float hmr = s_h[2][j], hmi = s_h[3][j];
                ar = fmaf(har, wr, fmaf(-hai, wi, ar));
                ai = fmaf(har, wi, fmaf(hai, wr, ai));
                mr2 = fmaf(hmr, wr, fmaf(-hmi, wi, mr2));
                mi2 = fmaf(hmr, wi, fmaf(hmi, wr, mi2));
            }
            const float zr = ar + mr2;
            const float zi = ai + mi2;
            // next launch's apply blocks consume these; launch boundary = barrier
            g_gr[b * CC + tid] = 1.0f / (1.0f + expf(-zr));
            g_gi[b * CC + tid] = 1.0f / (1.0f + expf(-zi));
        }
    }
}

extern "C" void kernel_launch(void* const* d_in, const int* in_sizes, int n_in,
                              void* d_out, int out_size) {
    const float* xr  = (const float*)d_in[0];
    const float* xi  = (const float*)d_in[1];
    const float* w1r = (const float*)d_in[2];
    const float* w1i = (const float*)d_in[3];
    const float* b1r = (const float*)d_in[4];
    const float* b1i = (const float*)d_in[5];
    const float* w2r = (const float*)d_in[6];
    const float* w2i = (const float*)d_in[7];
    const float* b2r = (const float*)d_in[8];
    const float* b2i = (const float*)d_in[9];
    float* out = (float*)d_out;

    reset_kernel<<<1, 32>>>();
    // Software pipeline across launches: F(b) = pool(b) + gate(b) + apply(b-1).
    // Launch boundary guarantees gate(b-1) is visible to F(b)'s apply blocks.
    for (int b = 0; b <= BB; b++) {
        F_kernel<<<FGRID, NTHR>>>(b, xr, xi, out,
                                  w1r, w1i, b1r, b1i,
                                  w2r, w2i, b2r, b2i);
    }
}

// round 6
// speedup vs baseline: 1.0536x; 1.0536x over previous
#include <cuda_runtime.h>
#include <math_constants.h>

#define BB 16
#define CC 256
#define RR 64
#define HW 16384
#define HW4 (HW / 4)                 // 4096 float4 per plane per component
#define HALF4 (HW4 / 2)              // 2048 float4 per half-plane
#define NPLANE (BB * CC)
#define NEG_SLOPE 0.01f

#define NTHR 256
#define POOLB 512                    // bids [0,512): pool half-plane blocks
#define GATEB 512                    // bid 512: gate block (batch k-1)
#define APPLY0 513                   // bids [513,1025): apply half-plane blocks
#define NAPPLY 512
#define FGRID (APPLY0 + NAPPLY)      // 1025 blocks -> single co-resident wave

// ---- scratch (__device__ globals; allocation-free rule) ----
// Per-batch partials: pool(k) writes them in PA(k); gate(k) reads them in
// PA(k+1). Distinct batch slots -> no same-launch read/write conflict.
__device__ float g_hsr[BB][POOLB], g_hsi[BB][POOLB];
__device__ float g_hmr[BB][POOLB], g_hmi[BB][POOLB];
__device__ float g_gr[NPLANE], g_gi[NPLANE];

__global__ __launch_bounds__(NTHR) void PA_kernel(
    int k,
    const float* __restrict__ xr, const float* __restrict__ xi,
    float* __restrict__ out,
    const float* __restrict__ w1r, const float* __restrict__ w1i,
    const float* __restrict__ b1r, const float* __restrict__ b1i,
    const float* __restrict__ w2r, const float* __restrict__ w2i,
    const float* __restrict__ b2r, const float* __restrict__ b2i)
{
    const int bid = blockIdx.x;
    const int tid = threadIdx.x;

    // ================= APPLY batch k-2 (plain loads/stores) =================
    if (bid >= APPLY0) {
        const int ab = k - 2;
        if (ab < 0 || ab >= BB) return;
        const int blk = bid - APPLY0;               // 0..511
        const int c = blk >> 1;                     // channel
        const int half = blk & 1;
        const float gr = g_gr[ab * CC + c];         // written in PA(k-1)
        const float gi = g_gi[ab * CC + c];

        const size_t base = ((size_t)(ab * CC + c)) * HW4 + (size_t)half * HALF4;
        const float4* pr = reinterpret_cast<const float4*>(xr) + base;
        const float4* pi = reinterpret_cast<const float4*>(xi) + base;
        float4* por = reinterpret_cast<float4*>(out) + base;
        float4* poi = reinterpret_cast<float4*>(out) + (size_t)NPLANE * HW4 + base;

#pragma unroll
        for (int it = 0; it < HALF4 / NTHR; it++) {   // 8 iters
            const int i = it * NTHR + tid;
            const float4 a = pr[i];                   // expect L2 hit (pooled 2 launches ago)
            const float4 bv = pi[i];
            float4 r, m;
            r.x = fmaf(a.x, gr, -bv.x * gi);
            r.y = fmaf(a.y, gr, -bv.y * gi);
            r.z = fmaf(a.z, gr, -bv.z * gi);
            r.w = fmaf(a.w, gr, -bv.w * gi);
            m.x = fmaf(a.x, gi, bv.x * gr);
            m.y = fmaf(a.y, gi, bv.y * gr);
            m.z = fmaf(a.z, gi, bv.z * gr);
            m.w = fmaf(a.w, gi, bv.w * gr);
            por[i] = r;                               // plain stores (R1 fast path)
            poi[i] = m;
        }
        return;
    }

    // ================= POOL batch k (half-plane per block) ===================
    if (bid < POOLB) {
        if (k >= BB) return;
        const int c = bid >> 1;
        const size_t base = ((size_t)(k * CC + c)) * HW4 + (size_t)(bid & 1) * HALF4;
        const float4* pr = reinterpret_cast<const float4*>(xr) + base;
        const float4* pi = reinterpret_cast<const float4*>(xi) + base;

        float sr = 0.f, si = 0.f;
        float mr = -CUDART_INF_F, mi = -CUDART_INF_F;
#pragma unroll
        for (int it = 0; it < HALF4 / NTHR; it++) {   // 8 iters, plain loads
            const int i = it * NTHR + tid;
            const float4 a = pr[i];
            const float4 bv = pi[i];
            sr += (a.x + a.y) + (a.z + a.w);
            si += (bv.x + bv.y) + (bv.z + bv.w);
            mr = fmaxf(mr, fmaxf(fmaxf(a.x, a.y), fmaxf(a.z, a.w)));
            mi = fmaxf(mi, fmaxf(fmaxf(bv.x, bv.y), fmaxf(bv.z, bv.w)));
        }
#pragma unroll
        for (int o = 16; o > 0; o >>= 1) {
            sr += __shfl_down_sync(0xFFFFFFFFu, sr, o);
            si += __shfl_down_sync(0xFFFFFFFFu, si, o);
            mr = fmaxf(mr, __shfl_down_sync(0xFFFFFFFFu, mr, o));
            mi = fmaxf(mi, __shfl_down_sync(0xFFFFFFFFu, mi, o));
        }
        __shared__ float red_sr[8], red_si[8], red_mr[8], red_mi[8];
        const int wid = tid >> 5, lid = tid & 31;
        if (lid == 0) { red_sr[wid] = sr; red_si[wid] = si; red_mr[wid] = mr; red_mi[wid] = mi; }
        __syncthreads();
        if (tid == 0) {
            float tsr = red_sr[0], tsi = red_si[0], tmr = red_mr[0], tmi = red_mi[0];
#pragma unroll
            for (int w = 1; w < 8; w++) {
                tsr += red_sr[w]; tsi += red_si[w];
                tmr = fmaxf(tmr, red_mr[w]); tmi = fmaxf(tmi, red_mi[w]);
            }
            g_hsr[k][bid] = tsr; g_hsi[k][bid] = tsi;   // read next launch
            g_hmr[k][bid] = tmr; g_hmi[k][bid] = tmi;
        }
        return;
    }

    // ================= GATE batch k-1 (bid == 512, no spin) ==================
    {
        const int gb = k - 1;
        if (gb < 0 || gb >= BB) return;

        __shared__ float s_in[4][CC];
        __shared__ float s_h[4][RR];
        {   // combine half-plane partials from PA(k-1) -> pooled channel values
            const int h0 = 2 * tid, h1 = 2 * tid + 1;
            s_in[0][tid] = (g_hsr[gb][h0] + g_hsr[gb][h1]) * (1.0f / HW);
            s_in[1][tid] = (g_hsi[gb][h0] + g_hsi[gb][h1]) * (1.0f / HW);
            s_in[2][tid] = fmaxf(g_hmr[gb][h0], g_hmr[gb][h1]);
            s_in[3][tid] = fmaxf(g_hmi[gb][h0], g_hmi[gb][h1]);
        }
        __syncthreads();

        if (tid < 2 * RR) {   // layer 1 + complex LeakyReLU: {avg,max} x 64
            const int which = tid >> 6;
            const int r = tid & (RR - 1);
            const float* zr = s_in[2 * which];
            const float* zi = s_in[2 * which + 1];
            float yr = b1r[r], yi = b1i[r];
#pragma unroll 8
            for (int c = 0; c < CC; c++) {
                const float wr = w1r[r * CC + c];
                const float wi = w1i[r * CC + c];
                const float zrc = zr[c], zic = zi[c];
                yr = fmaf(zrc, wr, fmaf(-zic, wi, yr));
                yi = fmaf(zrc, wi, fmaf(zic, wr, yi));
            }
            yr = (yr > 0.f) ? yr : NEG_SLOPE * yr;
            yi = (yi > 0.f) ? yi : NEG_SLOPE * yi;
            s_h[2 * which][r] = yr;
            s_h[2 * which + 1][r] = yi;
        }
        __syncthreads();

        {   // layer 2 both branches + sigmoid; thread = output channel
            float ar = b2r[tid], ai = b2i[tid];
            float mr2 = ar, mi2 = ai;
#pragma unroll 8
            for (int j = 0; j < RR; j++) {
                const float wr = w2r[tid * RR + j];
                const float wi = w2i[tid * RR + j];
                const float har = s_h[0][j], hai = s_h[1][j];
                const float hmr = s_h[2][j], hmi = s_h[3][j];
                ar = fmaf(har, wr, fmaf(-hai, wi, ar));
                ai = fmaf(har, wi, fmaf(hai, wr, ai));
                mr2 = fmaf(hmr, wr, fmaf(-hmi, wi, mr2));
                mi2 = fmaf(hmr, wi, fmaf(hmi, wr, mi2));
            }
            const float zr = ar + mr2;
            const float zi = ai + mi2;
            // consumed by apply blocks in PA(k+1); launch boundary = barrier
            g_gr[gb * CC + tid] = 1.0f / (1.0f + expf(-zr));
            g_gi[gb * CC + tid] = 1.0f / (1.0f + expf(-zi));
        }
    }
}

extern "C" void kernel_launch(void* const* d_in, const int* in_sizes, int n_in,
                              void* d_out, int out_size) {
    const float* xr  = (const float*)d_in[0];
    const float* xi  = (const float*)d_in[1];
    const float* w1r = (const float*)d_in[2];
    const float* w1i = (const float*)d_in[3];
    const float* b1r = (const float*)d_in[4];
    const float* b1i = (const float*)d_in[5];
    const float* w2r = (const float*)d_in[6];
    const float* w2i = (const float*)d_in[7];
    const float* b2r = (const float*)d_in[8];
    const float* b2i = (const float*)d_in[9];
    float* out = (float*)d_out;

    // Depth-2 software pipeline across launch boundaries:
    // PA(k) = pool(k) + gate(k-1) + apply(k-2). All dependencies cross a
    // launch boundary -> no atomics, no spinning, no fences anywhere.
    for (int k = 0; k < BB + 2; k++) {
        PA_kernel<<<FGRID, NTHR>>>(k, xr, xi, out,
                                   w1r, w1i, b1r, b1i,
                                   w2r, w2i, b2r, b2i);
    }
}

// round 7
// speedup vs baseline: 1.4080x; 1.3364x over previous
#include <cuda_runtime.h>
#include <math_constants.h>

#define BB 16
#define CC 256
#define RR 64
#define HW 16384
#define HW4 (HW / 4)                 // 4096 float4 per plane per component
#define HALF4 (HW4 / 2)              // 2048 float4 per half-plane
#define NPLANE (BB * CC)
#define NEG_SLOPE 0.01f

#define NTHR 256
#define POOLB 512                    // bids [0,512): pool half-plane blocks
#define APPLY0 513                   // bids [513,1025): apply half-plane blocks
#define NAPPLY 512
#define FGRID (APPLY0 + NAPPLY)      // 1025 blocks -> single co-resident wave

// ---- scratch (__device__ globals; allocation-free rule) ----
__device__ float g_hsr[BB][POOLB], g_hsi[BB][POOLB];   // half-plane sums
__device__ float g_hmr[BB][POOLB], g_hmi[BB][POOLB];   // half-plane maxes
__device__ float g_gr[NPLANE], g_gi[NPLANE];           // gates

__global__ __launch_bounds__(NTHR) void PA_kernel(
    int k,
    const float* __restrict__ xr, const float* __restrict__ xi,
    float* __restrict__ out,
    const float* __restrict__ w1r, const float* __restrict__ w1i,
    const float* __restrict__ b1r, const float* __restrict__ b1i,
    const float* __restrict__ w2r, const float* __restrict__ w2i,
    const float* __restrict__ b2r, const float* __restrict__ b2i)
{
    const int bid = blockIdx.x;
    const int tid = threadIdx.x;

    // ================= APPLY batch k-2 =================
    if (bid >= APPLY0) {
        const int ab = k - 2;
        if (ab < 0 || ab >= BB) return;
        const int blk = bid - APPLY0;               // 0..511
        const int c = blk >> 1;
        const int half = blk & 1;
        const float gr = g_gr[ab * CC + c];         // written in PA(k-1)
        const float gi = g_gi[ab * CC + c];

        const size_t base = ((size_t)(ab * CC + c)) * HW4 + (size_t)half * HALF4;
        const float4* pr = reinterpret_cast<const float4*>(xr) + base;
        const float4* pi = reinterpret_cast<const float4*>(xi) + base;
        float4* por = reinterpret_cast<float4*>(out) + base;
        float4* poi = reinterpret_cast<float4*>(out) + (size_t)NPLANE * HW4 + base;

#pragma unroll
        for (int it = 0; it < HALF4 / NTHR; it++) {   // 8 iters
            const int i = it * NTHR + tid;
            const float4 a  = __ldcs(pr + i);   // L2 hit expected; evict-first after
            const float4 bv = __ldcs(pi + i);
            float4 r, m;
            r.x = fmaf(a.x, gr, -bv.x * gi);
            r.y = fmaf(a.y, gr, -bv.y * gi);
            r.z = fmaf(a.z, gr, -bv.z * gi);
            r.w = fmaf(a.w, gr, -bv.w * gi);
            m.x = fmaf(a.x, gi, bv.x * gr);
            m.y = fmaf(a.y, gi, bv.y * gr);
            m.z = fmaf(a.z, gi, bv.z * gr);
            m.w = fmaf(a.w, gi, bv.w * gr);
            __stcs(por + i, r);                 // streaming: keep L2 for x
            __stcs(poi + i, m);
        }
        return;
    }

    // ================= POOL batch k (half-plane per block) ===================
    if (bid < POOLB) {
        if (k >= BB) return;
        const int c = bid >> 1;
        const size_t base = ((size_t)(k * CC + c)) * HW4 + (size_t)(bid & 1) * HALF4;
        const float4* pr = reinterpret_cast<const float4*>(xr) + base;
        const float4* pi = reinterpret_cast<const float4*>(xi) + base;

        float sr = 0.f, si = 0.f;
        float mr = -CUDART_INF_F, mi = -CUDART_INF_F;
#pragma unroll
        for (int it = 0; it < HALF4 / NTHR; it++) {   // 8 iters; allocate in L2
            const int i = it * NTHR + tid;
            const float4 a  = __ldcg(pr + i);
            const float4 bv = __ldcg(pi + i);
            sr += (a.x + a.y) + (a.z + a.w);
            si += (bv.x + bv.y) + (bv.z + bv.w);
            mr = fmaxf(mr, fmaxf(fmaxf(a.x, a.y), fmaxf(a.z, a.w)));
            mi = fmaxf(mi, fmaxf(fmaxf(bv.x, bv.y), fmaxf(bv.z, bv.w)));
        }
#pragma unroll
        for (int o = 16; o > 0; o >>= 1) {
            sr += __shfl_down_sync(0xFFFFFFFFu, sr, o);
            si += __shfl_down_sync(0xFFFFFFFFu, si, o);
            mr = fmaxf(mr, __shfl_down_sync(0xFFFFFFFFu, mr, o));
            mi = fmaxf(mi, __shfl_down_sync(0xFFFFFFFFu, mi, o));
        }
        __shared__ float red_sr[8], red_si[8], red_mr[8], red_mi[8];
        const int wid = tid >> 5, lid = tid & 31;
        if (lid == 0) { red_sr[wid] = sr; red_si[wid] = si; red_mr[wid] = mr; red_mi[wid] = mi; }
        __syncthreads();
        if (tid == 0) {
            float tsr = red_sr[0], tsi = red_si[0], tmr = red_mr[0], tmi = red_mi[0];
#pragma unroll
            for (int w = 1; w < 8; w++) {
                tsr += red_sr[w]; tsi += red_si[w];
                tmr = fmaxf(tmr, red_mr[w]); tmi = fmaxf(tmi, red_mi[w]);
            }
            g_hsr[k][bid] = tsr; g_hsi[k][bid] = tsi;   // read next launch
            g_hmr[k][bid] = tmr; g_hmi[k][bid] = tmi;
        }
        return;
    }

    // ================= GATE batch k-1 (bid == 512) — COALESCED MLP ===========
    // Warp-per-output: lanes sweep the contraction dim -> every weight LDG is
    // one 128B line (was 32 lines/LDG = the 55us serial bottleneck).
    {
        const int gb = k - 1;
        if (gb < 0 || gb >= BB) return;
        const int wid = tid >> 5;    // 0..7
        const int lane = tid & 31;

        __shared__ float s_in[4][CC];   // avg_r, avg_i, max_r, max_i
        __shared__ float s_h[4][RR];    // hidden (post-LeakyReLU)
        {   // combine half-plane partials from PA(k-1)
            const int h0 = 2 * tid, h1 = 2 * tid + 1;
            s_in[0][tid] = (g_hsr[gb][h0] + g_hsr[gb][h1]) * (1.0f / HW);
            s_in[1][tid] = (g_hsi[gb][h0] + g_hsi[gb][h1]) * (1.0f / HW);
            s_in[2][tid] = fmaxf(g_hmr[gb][h0], g_hmr[gb][h1]);
            s_in[3][tid] = fmaxf(g_hmi[gb][h0], g_hmi[gb][h1]);
        }
        __syncthreads();

        // ---- layer 1: 128 outputs ({avg,max} x 64), 16 per warp ----
#pragma unroll
        for (int i = 0; i < 16; i++) {
            const int o = wid * 16 + i;
            const int which = o >> 6;
            const int r = o & (RR - 1);
            const float* zr = s_in[2 * which];
            const float* zi = s_in[2 * which + 1];
            float yr = 0.f, yi = 0.f;
#pragma unroll
            for (int cc = 0; cc < CC / 32; cc++) {   // 8 coalesced iterations
                const int c = cc * 32 + lane;
                const float wr = w1r[r * CC + c];    // lane-consecutive: 1 line
                const float wi = w1i[r * CC + c];
                const float zrc = zr[c], zic = zi[c];
                yr = fmaf(zrc, wr, fmaf(-zic, wi, yr));
                yi = fmaf(zrc, wi, fmaf(zic, wr, yi));
            }
#pragma unroll
            for (int o2 = 16; o2 > 0; o2 >>= 1) {
                yr += __shfl_down_sync(0xFFFFFFFFu, yr, o2);
                yi += __shfl_down_sync(0xFFFFFFFFu, yi, o2);
            }
            if (lane == 0) {
                yr += b1r[r]; yi += b1i[r];
                yr = (yr > 0.f) ? yr : NEG_SLOPE * yr;
                yi = (yi > 0.f) ? yi : NEG_SLOPE * yi;
                s_h[2 * which][r] = yr;
                s_h[2 * which + 1][r] = yi;
            }
        }
        __syncthreads();

        // ---- layer 2: 256 channels, 32 per warp; both branches fused ----
#pragma unroll
        for (int i = 0; i < 32; i++) {
            const int t = wid * 32 + i;
            float ar = 0.f, ai = 0.f, mr2 = 0.f, mi2 = 0.f;
#pragma unroll
            for (int jj = 0; jj < RR / 32; jj++) {   // 2 coalesced iterations
                const int j = jj * 32 + lane;
                const float wr = w2r[t * RR + j];    // lane-consecutive: 1 line
                const float wi = w2i[t * RR + j];
                const float har = s_h[0][j], hai = s_h[1][j];
                const float hmr = s_h[2][j], hmi = s_h[3][j];
                ar  = fmaf(har, wr, fmaf(-hai, wi, ar));
                ai  = fmaf(har, wi, fmaf(hai, wr, ai));
                mr2 = fmaf(hmr, wr, fmaf(-hmi, wi, mr2));
                mi2 = fmaf(hmr, wi, fmaf(hmi, wr, mi2));
            }
#pragma unroll
            for (int o2 = 16; o2 > 0; o2 >>= 1) {
                ar  += __shfl_down_sync(0xFFFFFFFFu, ar, o2);
                ai  += __shfl_down_sync(0xFFFFFFFFu, ai, o2);
                mr2 += __shfl_down_sync(0xFFFFFFFFu, mr2, o2);
                mi2 += __shfl_down_sync(0xFFFFFFFFu, mi2, o2);
            }
            if (lane == 0) {
                const float zr = (ar + b2r[t]) + (mr2 + b2r[t]);
                const float zi = (ai + b2i[t]) + (mi2 + b2i[t]);
                // consumed by apply blocks in PA(k+1); launch boundary = barrier
                g_gr[gb * CC + t] = 1.0f / (1.0f + expf(-zr));
                g_gi[gb * CC + t] = 1.0f / (1.0f + expf(-zi));
            }
        }
    }
}

extern "C" void kernel_launch(void* const* d_in, const int* in_sizes, int n_in,
                              void* d_out, int out_size) {
    const float* xr  = (const float*)d_in[0];
    const float* xi  = (const float*)d_in[1];
    const float* w1r = (const float*)d_in[2];
    const float* w1i = (const float*)d_in[3];
    const float* b1r = (const float*)d_in[4];
    const float* b1i = (const float*)d_in[5];
    const float* w2r = (const float*)d_in[6];
    const float* w2i = (const float*)d_in[7];
    const float* b2r = (const float*)d_in[8];
    const float* b2i = (const float*)d_in[9];
    float* out = (float*)d_out;

    // Depth-2 software pipeline across launch boundaries:
    // PA(k) = pool(k) + gate(k-1) + apply(k-2). All dependencies cross a
    // launch boundary -> no atomics, no spinning, no fences anywhere.
    for (int k = 0; k < BB + 2; k++) {
        PA_kernel<<<FGRID, NTHR>>>(k, xr, xi, out,
                                   w1r, w1i, b1r, b1i,
                                   w2r, w2i, b2r, b2i);
    }
}

// round 8
// speedup vs baseline: 3.8325x; 2.7219x over previous
#include <cuda_runtime.h>
#include <math_constants.h>

#define BB 16
#define CC 256
#define RR 64
#define HW 16384
#define HW4 (HW / 4)
#define NPLANE (BB * CC)             // 4096
#define NEG_SLOPE 0.01f

// Scratch (__device__ globals; allocation-free rule)
__device__ float g_avg_r[NPLANE], g_avg_i[NPLANE];
__device__ float g_max_r[NPLANE], g_max_i[NPLANE];
__device__ float g_gr[NPLANE], g_gi[NPLANE];

// ---------------------------------------------------------------------------
// Kernel 1: per-plane mean + max pooling. One block per (b,c) plane.
// (R1 version verbatim: measured 86% DRAM, 6.75 TB/s.)
// ---------------------------------------------------------------------------
__global__ __launch_bounds__(256) void pool_kernel(const float* __restrict__ xr,
                                                   const float* __restrict__ xi) {
    const int plane = blockIdx.x;
    const float4* pr = reinterpret_cast<const float4*>(xr) + (size_t)plane * HW4;
    const float4* pi = reinterpret_cast<const float4*>(xi) + (size_t)plane * HW4;

    float sr = 0.f, si = 0.f;
    float mr = -CUDART_INF_F, mi = -CUDART_INF_F;

#pragma unroll 4
    for (int i = threadIdx.x; i < HW4; i += 256) {
        float4 a = pr[i];
        float4 b = pi[i];
        sr += (a.x + a.y) + (a.z + a.w);
        si += (b.x + b.y) + (b.z + b.w);
        mr = fmaxf(mr, fmaxf(fmaxf(a.x, a.y), fmaxf(a.z, a.w)));
        mi = fmaxf(mi, fmaxf(fmaxf(b.x, b.y), fmaxf(b.z, b.w)));
    }
#pragma unroll
    for (int o = 16; o > 0; o >>= 1) {
        sr += __shfl_down_sync(0xFFFFFFFFu, sr, o);
        si += __shfl_down_sync(0xFFFFFFFFu, si, o);
        mr = fmaxf(mr, __shfl_down_sync(0xFFFFFFFFu, mr, o));
        mi = fmaxf(mi, __shfl_down_sync(0xFFFFFFFFu, mi, o));
    }
    __shared__ float s_sr[8], s_si[8], s_mr[8], s_mi[8];
    const int wid = threadIdx.x >> 5;
    const int lid = threadIdx.x & 31;
    if (lid == 0) { s_sr[wid] = sr; s_si[wid] = si; s_mr[wid] = mr; s_mi[wid] = mi; }
    __syncthreads();
    if (threadIdx.x == 0) {
        float tsr = s_sr[0], tsi = s_si[0], tmr = s_mr[0], tmi = s_mi[0];
#pragma unroll
        for (int w = 1; w < 8; w++) {
            tsr += s_sr[w]; tsi += s_si[w];
            tmr = fmaxf(tmr, s_mr[w]); tmi = fmaxf(tmi, s_mi[w]);
        }
        g_avg_r[plane] = tsr * (1.0f / HW);
        g_avg_i[plane] = tsi * (1.0f / HW);
        g_max_r[plane] = tmr;
        g_max_i[plane] = tmi;
    }
}

// ---------------------------------------------------------------------------
// Kernel 2: gate MLP, coalesced (warp-per-output, lanes sweep contraction dim;
// every weight LDG is one 128B line). One block per batch, 8 warps, ~5us.
// ---------------------------------------------------------------------------
__global__ __launch_bounds__(256) void gate_kernel(
    const float* __restrict__ w1r, const float* __restrict__ w1i,
    const float* __restrict__ b1r, const float* __restrict__ b1i,
    const float* __restrict__ w2r, const float* __restrict__ w2i,
    const float* __restrict__ b2r, const float* __restrict__ b2i) {
    const int b = blockIdx.x;
    const int tid = threadIdx.x;
    const int wid = tid >> 5;
    const int lane = tid & 31;

    __shared__ float s_in[4][CC];   // avg_r, avg_i, max_r, max_i
    __shared__ float s_h[4][RR];    // hidden (post-LeakyReLU)

    s_in[0][tid] = g_avg_r[b * CC + tid];
    s_in[1][tid] = g_avg_i[b * CC + tid];
    s_in[2][tid] = g_max_r[b * CC + tid];
    s_in[3][tid] = g_max_i[b * CC + tid];
    __syncthreads();

    // ---- layer 1: 128 outputs ({avg,max} x 64), 16 per warp ----
#pragma unroll
    for (int i = 0; i < 16; i++) {
        const int o = wid * 16 + i;
        const int which = o >> 6;          // 0 = avg, 1 = max
        const int r = o & (RR - 1);
        const float* zr = s_in[2 * which];
        const float* zi = s_in[2 * which + 1];
        float yr = 0.f, yi = 0.f;
#pragma unroll
        for (int cc = 0; cc < CC / 32; cc++) {   // 8 coalesced iterations
            const int c = cc * 32 + lane;
            const float wr = w1r[r * CC + c];
            const float wi = w1i[r * CC + c];
            const float zrc = zr[c], zic = zi[c];
            yr = fmaf(zrc, wr, fmaf(-zic, wi, yr));
            yi = fmaf(zrc, wi, fmaf(zic, wr, yi));
        }
#pragma unroll
        for (int o2 = 16; o2 > 0; o2 >>= 1) {
            yr += __shfl_down_sync(0xFFFFFFFFu, yr, o2);
            yi += __shfl_down_sync(0xFFFFFFFFu, yi, o2);
        }
        if (lane == 0) {
            yr += b1r[r]; yi += b1i[r];
            yr = (yr > 0.f) ? yr : NEG_SLOPE * yr;
            yi = (yi > 0.f) ? yi : NEG_SLOPE * yi;
            s_h[2 * which][r] = yr;
            s_h[2 * which + 1][r] = yi;
        }
    }
    __syncthreads();

    // ---- layer 2: 256 channels, 32 per warp; both branches fused ----
#pragma unroll
    for (int i = 0; i < 32; i++) {
        const int t = wid * 32 + i;
        float ar = 0.f, ai = 0.f, mr2 = 0.f, mi2 = 0.f;
#pragma unroll
        for (int jj = 0; jj < RR / 32; jj++) {   // 2 coalesced iterations
            const int j = jj * 32 + lane;
            const float wr = w2r[t * RR + j];
            const float wi = w2i[t * RR + j];
            const float har = s_h[0][j], hai = s_h[1][j];
            const float hmr = s_h[2][j], hmi = s_h[3][j];
            ar  = fmaf(har, wr, fmaf(-hai, wi, ar));
            ai  = fmaf(har, wi, fmaf(hai, wr, ai));
            mr2 = fmaf(hmr, wr, fmaf(-hmi, wi, mr2));
            mi2 = fmaf(hmr, wi, fmaf(hmi, wr, mi2));
        }
#pragma unroll
        for (int o2 = 16; o2 > 0; o2 >>= 1) {
            ar  += __shfl_down_sync(0xFFFFFFFFu, ar, o2);
            ai  += __shfl_down_sync(0xFFFFFFFFu, ai, o2);
            mr2 += __shfl_down_sync(0xFFFFFFFFu, mr2, o2);
            mi2 += __shfl_down_sync(0xFFFFFFFFu, mi2, o2);
        }
        if (lane == 0) {
            const float zr = (ar + b2r[t]) + (mr2 + b2r[t]);
            const float zi = (ai + b2i[t]) + (mi2 + b2i[t]);
            g_gr[b * CC + t] = 1.0f / (1.0f + expf(-zr));
            g_gi[b * CC + t] = 1.0f / (1.0f + expf(-zi));
        }
    }
}

// ---------------------------------------------------------------------------
// Kernel 3: complex multiply x * gate -> out[2,B,C,H,W].
// One block per plane, processed in REVERSE plane order: the pool kernel
// streamed x front-to-back, so L2 holds the tail of x when apply starts;
// reading tail-first converts ~120MB of DRAM reads into L2 hits.
// ---------------------------------------------------------------------------
__global__ __launch_bounds__(256) void apply_kernel(const float* __restrict__ xr,
                                                    const float* __restrict__ xi,
                                                    float* __restrict__ out) {
    const int plane = (NPLANE - 1) - blockIdx.x;   // reverse order
    const float gr = g_gr[plane];
    const float gi = g_gi[plane];

    const float4* pr = reinterpret_cast<const float4*>(xr) + (size_t)plane * HW4;
    const float4* pi = reinterpret_cast<const float4*>(xi) + (size_t)plane * HW4;
    float4* po_r = reinterpret_cast<float4*>(out) + (size_t)plane * HW4;
    float4* po_i = reinterpret_cast<float4*>(out) + (size_t)NPLANE * HW4 + (size_t)plane * HW4;

#pragma unroll 4
    for (int i = threadIdx.x; i < HW4; i += 256) {
        float4 a = pr[i];
        float4 b = pi[i];
        float4 r, m;
        r.x = fmaf(a.x, gr, -b.x * gi);
        r.y = fmaf(a.y, gr, -b.y * gi);
        r.z = fmaf(a.z, gr, -b.z * gi);
        r.w = fmaf(a.w, gr, -b.w * gi);
        m.x = fmaf(a.x, gi, b.x * gr);
        m.y = fmaf(a.y, gi, b.y * gr);
        m.z = fmaf(a.z, gi, b.z * gr);
        m.w = fmaf(a.w, gi, b.w * gr);
        po_r[i] = r;
        po_i[i] = m;
    }
}

extern "C" void kernel_launch(void* const* d_in, const int* in_sizes, int n_in,
                              void* d_out, int out_size) {
    const float* xr  = (const float*)d_in[0];
    const float* xi  = (const float*)d_in[1];
    const float* w1r = (const float*)d_in[2];
    const float* w1i = (const float*)d_in[3];
    const float* b1r = (const float*)d_in[4];
    const float* b1i = (const float*)d_in[5];
    const float* w2r = (const float*)d_in[6];
    const float* w2i = (const float*)d_in[7];
    const float* b2r = (const float*)d_in[8];
    const float* b2i = (const float*)d_in[9];
    float* out = (float*)d_out;

    pool_kernel<<<NPLANE, 256>>>(xr, xi);
    gate_kernel<<<BB, 256>>>(w1r, w1i, b1r, b1i, w2r, w2i, b2r, b2i);
    apply_kernel<<<NPLANE, 256>>>(xr, xi, out);
}

// round 9
// speedup vs baseline: 3.8671x; 1.0090x over previous
#include <cuda_runtime.h>
#include <math_constants.h>

#define BB 16
#define CC 256
#define RR 64
#define HW 16384
#define HW4 (HW / 4)                 // 4096 float4 per plane per component
#define HALF4 (HW4 / 2)              // 2048 float4 per half-plane
#define NPLANE (BB * CC)             // 4096
#define NHALF (NPLANE * 2)           // 8192 half-planes
#define NEG_SLOPE 0.01f

// Scratch (__device__ globals; allocation-free rule)
__device__ float g_hsr[NHALF], g_hsi[NHALF];   // half-plane sums
__device__ float g_hmr[NHALF], g_hmi[NHALF];   // half-plane maxes
__device__ float g_gr[NPLANE], g_gi[NPLANE];   // gates

// ---------------------------------------------------------------------------
// Kernel 1: per-HALF-plane mean + max pooling. 8192 blocks -> ~6.9 waves,
// minimal tail quantization (R8's 4096 blocks = 3.46 waves wasted ~10us).
// ---------------------------------------------------------------------------
__global__ __launch_bounds__(256) void pool_kernel(const float* __restrict__ xr,
                                                   const float* __restrict__ xi) {
    const int hp = blockIdx.x;                       // half-plane id
    const size_t base = (size_t)hp * HALF4;
    const float4* pr = reinterpret_cast<const float4*>(xr) + base;
    const float4* pi = reinterpret_cast<const float4*>(xi) + base;

    float sr = 0.f, si = 0.f;
    float mr = -CUDART_INF_F, mi = -CUDART_INF_F;

#pragma unroll
    for (int it = 0; it < HALF4 / 256; it++) {       // 8 iters
        const int i = it * 256 + threadIdx.x;
        float4 a = pr[i];
        float4 b = pi[i];
        sr += (a.x + a.y) + (a.z + a.w);
        si += (b.x + b.y) + (b.z + b.w);
        mr = fmaxf(mr, fmaxf(fmaxf(a.x, a.y), fmaxf(a.z, a.w)));
        mi = fmaxf(mi, fmaxf(fmaxf(b.x, b.y), fmaxf(b.z, b.w)));
    }
#pragma unroll
    for (int o = 16; o > 0; o >>= 1) {
        sr += __shfl_down_sync(0xFFFFFFFFu, sr, o);
        si += __shfl_down_sync(0xFFFFFFFFu, si, o);
        mr = fmaxf(mr, __shfl_down_sync(0xFFFFFFFFu, mr, o));
        mi = fmaxf(mi, __shfl_down_sync(0xFFFFFFFFu, mi, o));
    }
    __shared__ float s_sr[8], s_si[8], s_mr[8], s_mi[8];
    const int wid = threadIdx.x >> 5;
    const int lid = threadIdx.x & 31;
    if (lid == 0) { s_sr[wid] = sr; s_si[wid] = si; s_mr[wid] = mr; s_mi[wid] = mi; }
    __syncthreads();
    if (threadIdx.x == 0) {
        float tsr = s_sr[0], tsi = s_si[0], tmr = s_mr[0], tmi = s_mi[0];
#pragma unroll
        for (int w = 1; w < 8; w++) {
            tsr += s_sr[w]; tsi += s_si[w];
            tmr = fmaxf(tmr, s_mr[w]); tmi = fmaxf(tmi, s_mi[w]);
        }
        g_hsr[hp] = tsr; g_hsi[hp] = tsi;
        g_hmr[hp] = tmr; g_hmi[hp] = tmi;
    }
}

// ---------------------------------------------------------------------------
// Kernel 2: gate MLP (coalesced warp-per-output; R8-proven). One block per
// batch. Combines half-plane partials on load.
// ---------------------------------------------------------------------------
__global__ __launch_bounds__(256) void gate_kernel(
    const float* __restrict__ w1r, const float* __restrict__ w1i,
    const float* __restrict__ b1r, const float* __restrict__ b1i,
    const float* __restrict__ w2r, const float* __restrict__ w2i,
    const float* __restrict__ b2r, const float* __restrict__ b2i) {
    const int b = blockIdx.x;
    const int tid = threadIdx.x;
    const int wid = tid >> 5;
    const int lane = tid & 31;

    __shared__ float s_in[4][CC];   // avg_r, avg_i, max_r, max_i
    __shared__ float s_h[4][RR];    // hidden (post-LeakyReLU)

    {   // combine half-plane partials -> pooled per-channel values
        const int h0 = (b * CC + tid) * 2;
        s_in[0][tid] = (g_hsr[h0] + g_hsr[h0 + 1]) * (1.0f / HW);
        s_in[1][tid] = (g_hsi[h0] + g_hsi[h0 + 1]) * (1.0f / HW);
        s_in[2][tid] = fmaxf(g_hmr[h0], g_hmr[h0 + 1]);
        s_in[3][tid] = fmaxf(g_hmi[h0], g_hmi[h0 + 1]);
    }
    __syncthreads();

    // ---- layer 1: 128 outputs ({avg,max} x 64), 16 per warp ----
#pragma unroll
    for (int i = 0; i < 16; i++) {
        const int o = wid * 16 + i;
        const int which = o >> 6;          // 0 = avg, 1 = max
        const int r = o & (RR - 1);
        const float* zr = s_in[2 * which];
        const float* zi = s_in[2 * which + 1];
        float yr = 0.f, yi = 0.f;
#pragma unroll
        for (int cc = 0; cc < CC / 32; cc++) {   // 8 coalesced iterations
            const int c = cc * 32 + lane;
            const float wr = w1r[r * CC + c];
            const float wi = w1i[r * CC + c];
            const float zrc = zr[c], zic = zi[c];
            yr = fmaf(zrc, wr, fmaf(-zic, wi, yr));
            yi = fmaf(zrc, wi, fmaf(zic, wr, yi));
        }
#pragma unroll
        for (int o2 = 16; o2 > 0; o2 >>= 1) {
            yr += __shfl_down_sync(0xFFFFFFFFu, yr, o2);
            yi += __shfl_down_sync(0xFFFFFFFFu, yi, o2);
        }
        if (lane == 0) {
            yr += b1r[r]; yi += b1i[r];
            yr = (yr > 0.f) ? yr : NEG_SLOPE * yr;
            yi = (yi > 0.f) ? yi : NEG_SLOPE * yi;
            s_h[2 * which][r] = yr;
            s_h[2 * which + 1][r] = yi;
        }
    }
    __syncthreads();

    // ---- layer 2: 256 channels, 32 per warp; both branches fused ----
#pragma unroll
    for (int i = 0; i < 32; i++) {
        const int t = wid * 32 + i;
        float ar = 0.f, ai = 0.f, mr2 = 0.f, mi2 = 0.f;
#pragma unroll
        for (int jj = 0; jj < RR / 32; jj++) {   // 2 coalesced iterations
            const int j = jj * 32 + lane;
            const float wr = w2r[t * RR + j];
            const float wi = w2i[t * RR + j];
            const float har = s_h[0][j], hai = s_h[1][j];
            const float hmr = s_h[2][j], hmi = s_h[3][j];
            ar  = fmaf(har, wr, fmaf(-hai, wi, ar));
            ai  = fmaf(har, wi, fmaf(hai, wr, ai));
            mr2 = fmaf(hmr, wr, fmaf(-hmi, wi, mr2));
            mi2 = fmaf(hmr, wi, fmaf(hmi, wr, mi2));
        }
#pragma unroll
        for (int o2 = 16; o2 > 0; o2 >>= 1) {
            ar  += __shfl_down_sync(0xFFFFFFFFu, ar, o2);
            ai  += __shfl_down_sync(0xFFFFFFFFu, ai, o2);
            mr2 += __shfl_down_sync(0xFFFFFFFFu, mr2, o2);
            mi2 += __shfl_down_sync(0xFFFFFFFFu, mi2, o2);
        }
        if (lane == 0) {
            const float zr = (ar + b2r[t]) + (mr2 + b2r[t]);
            const float zi = (ai + b2i[t]) + (mi2 + b2i[t]);
            g_gr[b * CC + t] = 1.0f / (1.0f + expf(-zr));
            g_gi[b * CC + t] = 1.0f / (1.0f + expf(-zi));
        }
    }
}

// ---------------------------------------------------------------------------
// Kernel 3: complex multiply x * gate -> out[2,B,C,H,W].
// 8192 half-plane blocks, REVERSE order: pool streamed x front-to-back, so
// L2 holds the tail of x; reading tail-first converts ~120MB of DRAM reads
// into L2 hits (R8-proven), and finer blocks shrink the tail wave.
// ---------------------------------------------------------------------------
__global__ __launch_bounds__(256) void apply_kernel(const float* __restrict__ xr,
                                                    const float* __restrict__ xi,
                                                    float* __restrict__ out) {
    const int blk = (NHALF - 1) - blockIdx.x;        // reverse half-plane order
    const int plane = blk >> 1;
    const float gr = g_gr[plane];
    const float gi = g_gi[plane];

    const size_t base = (size_t)blk * HALF4;
    const float4* pr = reinterpret_cast<const float4*>(xr) + base;
    const float4* pi = reinterpret_cast<const float4*>(xi) + base;
    float4* po_r = reinterpret_cast<float4*>(out) + base;
    float4* po_i = reinterpret_cast<float4*>(out) + (size_t)NPLANE * HW4 + base;

#pragma unroll
    for (int it = 0; it < HALF4 / 256; it++) {       // 8 iters
        const int i = it * 256 + threadIdx.x;
        float4 a = pr[i];
        float4 b = pi[i];
        float4 r, m;
        r.x = fmaf(a.x, gr, -b.x * gi);
        r.y = fmaf(a.y, gr, -b.y * gi);
        r.z = fmaf(a.z, gr, -b.z * gi);
        r.w = fmaf(a.w, gr, -b.w * gi);
        m.x = fmaf(a.x, gi, b.x * gr);
        m.y = fmaf(a.y, gi, b.y * gr);
        m.z = fmaf(a.z, gi, b.z * gr);
        m.w = fmaf(a.w, gi, b.w * gr);
        po_r[i] = r;
        po_i[i] = m;
    }
}

extern "C" void kernel_launch(void* const* d_in, const int* in_sizes, int n_in,
                              void* d_out, int out_size) {
    const float* xr  = (const float*)d_in[0];
    const float* xi  = (const float*)d_in[1];
    const float* w1r = (const float*)d_in[2];
    const float* w1i = (const float*)d_in[3];
    const float* b1r = (const float*)d_in[4];
    const float* b1i = (const float*)d_in[5];
    const float* w2r = (const float*)d_in[6];
    const float* w2i = (const float*)d_in[7];
    const float* b2r = (const float*)d_in[8];
    const float* b2i = (const float*)d_in[9];
    float* out = (float*)d_out;

    pool_kernel<<<NHALF, 256>>>(xr, xi);
    gate_kernel<<<BB, 256>>>(w1r, w1i, b1r, b1i, w2r, w2i, b2r, b2i);
    apply_kernel<<<NHALF, 256>>>(xr, xi, out);
}

// round 10
// speedup vs baseline: 4.1481x; 1.0726x over previous
#include <cuda_runtime.h>
#include <math_constants.h>

#define BB 16
#define CC 256
#define RR 64
#define HW 16384
#define HW4 (HW / 4)                 // 4096 float4 per plane per component
#define HALF4 (HW4 / 2)              // 2048 float4 per half-plane
#define NPLANE (BB * CC)             // 4096
#define NHALF (NPLANE * 2)           // 8192 half-planes
#define HALF_PER_BATCH (CC * 2)      // 512 half-planes per batch
#define NEG_SLOPE 0.01f

// Scratch (__device__ globals; allocation-free rule)
__device__ float g_hsr[NHALF], g_hsi[NHALF];   // half-plane sums
__device__ float g_hmr[NHALF], g_hmi[NHALF];   // half-plane maxes
__device__ float g_gr[NPLANE], g_gi[NPLANE];   // gates
__device__ int   g_cnt[BB];                    // per-batch completion counters

__global__ void reset_kernel() {
    if (threadIdx.x < BB) g_cnt[threadIdx.x] = 0;
}

// ---------------------------------------------------------------------------
// Kernel 1: per-HALF-plane mean+max pooling; the block that completes a
// batch's 512th half-plane computes that batch's gate MLP inline (coalesced
// warp-per-output, ~3us, hidden under remaining pool traffic).
// ---------------------------------------------------------------------------
__global__ __launch_bounds__(256) void pool_gate_kernel(
    const float* __restrict__ xr, const float* __restrict__ xi,
    const float* __restrict__ w1r, const float* __restrict__ w1i,
    const float* __restrict__ b1r, const float* __restrict__ b1i,
    const float* __restrict__ w2r, const float* __restrict__ w2i,
    const float* __restrict__ b2r, const float* __restrict__ b2i) {
    const int hp = blockIdx.x;                       // half-plane id
    const int batch = hp / HALF_PER_BATCH;
    const int tid = threadIdx.x;
    const int wid = tid >> 5;
    const int lane = tid & 31;

    {   // ---------------- pooling ----------------
        const size_t base = (size_t)hp * HALF4;
        const float4* pr = reinterpret_cast<const float4*>(xr) + base;
        const float4* pi = reinterpret_cast<const float4*>(xi) + base;

        float sr = 0.f, si = 0.f;
        float mr = -CUDART_INF_F, mi = -CUDART_INF_F;
#pragma unroll
        for (int it = 0; it < HALF4 / 256; it++) {   // 8 iters
            const int i = it * 256 + tid;
            float4 a = pr[i];
            float4 b = pi[i];
            sr += (a.x + a.y) + (a.z + a.w);
            si += (b.x + b.y) + (b.z + b.w);
            mr = fmaxf(mr, fmaxf(fmaxf(a.x, a.y), fmaxf(a.z, a.w)));
            mi = fmaxf(mi, fmaxf(fmaxf(b.x, b.y), fmaxf(b.z, b.w)));
        }
#pragma unroll
        for (int o = 16; o > 0; o >>= 1) {
            sr += __shfl_down_sync(0xFFFFFFFFu, sr, o);
            si += __shfl_down_sync(0xFFFFFFFFu, si, o);
            mr = fmaxf(mr, __shfl_down_sync(0xFFFFFFFFu, mr, o));
            mi = fmaxf(mi, __shfl_down_sync(0xFFFFFFFFu, mi, o));
        }
        __shared__ float s_sr[8], s_si[8], s_mr[8], s_mi[8];
        if (lane == 0) { s_sr[wid] = sr; s_si[wid] = si; s_mr[wid] = mr; s_mi[wid] = mi; }
        __syncthreads();
        if (tid == 0) {
            float tsr = s_sr[0], tsi = s_si[0], tmr = s_mr[0], tmi = s_mi[0];
#pragma unroll
            for (int w = 1; w < 8; w++) {
                tsr += s_sr[w]; tsi += s_si[w];
                tmr = fmaxf(tmr, s_mr[w]); tmi = fmaxf(tmi, s_mi[w]);
            }
            g_hsr[hp] = tsr; g_hsi[hp] = tsi;
            g_hmr[hp] = tmr; g_hmi[hp] = tmi;
        }
    }

    // ---------------- finisher election ----------------
    __shared__ int s_fin;
    __syncthreads();               // all pool smem writes done before reuse below
    if (tid == 0) {
        __threadfence();           // publish partials before counting
        s_fin = (atomicAdd(&g_cnt[batch], 1) == HALF_PER_BATCH - 1);
    }
    __syncthreads();
    if (!s_fin) return;
    __threadfence();               // acquire: other blocks' partials now visible

    // ---------------- gate MLP for `batch` (coalesced, R8-proven) ----------
    __shared__ float s_in[4][CC];
    __shared__ float s_h[4][RR];
    {
        const int h0 = (batch * CC + tid) * 2;
        s_in[0][tid] = (g_hsr[h0] + g_hsr[h0 + 1]) * (1.0f / HW);
        s_in[1][tid] = (g_hsi[h0] + g_hsi[h0 + 1]) * (1.0f / HW);
        s_in[2][tid] = fmaxf(g_hmr[h0], g_hmr[h0 + 1]);
        s_in[3][tid] = fmaxf(g_hmi[h0], g_hmi[h0 + 1]);
    }
    __syncthreads();

#pragma unroll
    for (int i = 0; i < 16; i++) {   // layer 1: 128 outputs, 16 per warp
        const int o = wid * 16 + i;
        const int which = o >> 6;
        const int r = o & (RR - 1);
        const float* zr = s_in[2 * which];
        const float* zi = s_in[2 * which + 1];
        float yr = 0.f, yi = 0.f;
#pragma unroll
        for (int cc = 0; cc < CC / 32; cc++) {
            const int c = cc * 32 + lane;
            const float wr = w1r[r * CC + c];
            const float wi = w1i[r * CC + c];
            const float zrc = zr[c], zic = zi[c];
            yr = fmaf(zrc, wr, fmaf(-zic, wi, yr));
            yi = fmaf(zrc, wi, fmaf(zic, wr, yi));
        }
#pragma unroll
        for (int o2 = 16; o2 > 0; o2 >>= 1) {
            yr += __shfl_down_sync(0xFFFFFFFFu, yr, o2);
            yi += __shfl_down_sync(0xFFFFFFFFu, yi, o2);
        }
        if (lane == 0) {
            yr += b1r[r]; yi += b1i[r];
            yr = (yr > 0.f) ? yr : NEG_SLOPE * yr;
            yi = (yi > 0.f) ? yi : NEG_SLOPE * yi;
            s_h[2 * which][r] = yr;
            s_h[2 * which + 1][r] = yi;
        }
    }
    __syncthreads();

#pragma unroll
    for (int i = 0; i < 32; i++) {   // layer 2: 256 channels, 32 per warp
        const int t = wid * 32 + i;
        float ar = 0.f, ai = 0.f, mr2 = 0.f, mi2 = 0.f;
#pragma unroll
        for (int jj = 0; jj < RR / 32; jj++) {
            const int j = jj * 32 + lane;
            const float wr = w2r[t * RR + j];
            const float wi = w2i[t * RR + j];
            const float har = s_h[0][j], hai = s_h[1][j];
            const float hmr = s_h[2][j], hmi = s_h[3][j];
            ar  = fmaf(har, wr, fmaf(-hai, wi, ar));
            ai  = fmaf(har, wi, fmaf(hai, wr, ai));
            mr2 = fmaf(hmr, wr, fmaf(-hmi, wi, mr2));
            mi2 = fmaf(hmr, wi, fmaf(hmi, wr, mi2));
        }
#pragma unroll
        for (int o2 = 16; o2 > 0; o2 >>= 1) {
            ar  += __shfl_down_sync(0xFFFFFFFFu, ar, o2);
            ai  += __shfl_down_sync(0xFFFFFFFFu, ai, o2);
            mr2 += __shfl_down_sync(0xFFFFFFFFu, mr2, o2);
            mi2 += __shfl_down_sync(0xFFFFFFFFu, mi2, o2);
        }
        if (lane == 0) {
            const float zr = (ar + b2r[t]) + (mr2 + b2r[t]);
            const float zi = (ai + b2i[t]) + (mi2 + b2i[t]);
            g_gr[batch * CC + t] = 1.0f / (1.0f + expf(-zr));
            g_gi[batch * CC + t] = 1.0f / (1.0f + expf(-zi));
        }
    }
    // consumed by apply_kernel; launch boundary = barrier
}

// ---------------------------------------------------------------------------
// Kernel 2: complex multiply x * gate -> out[2,B,C,H,W].
// Reverse half-plane order (L2-tail reuse). Loads plain (hit the resident
// tail); stores __stcs evict-first so output writes do NOT write-allocate
// and evict the x tail we are about to read.
// ---------------------------------------------------------------------------
__global__ __launch_bounds__(256) void apply_kernel(const float* __restrict__ xr,
                                                    const float* __restrict__ xi,
                                                    float* __restrict__ out) {
    const int blk = (NHALF - 1) - blockIdx.x;        // reverse half-plane order
    const int plane = blk >> 1;
    const float gr = g_gr[plane];
    const float gi = g_gi[plane];

    const size_t base = (size_t)blk * HALF4;
    const float4* pr = reinterpret_cast<const float4*>(xr) + base;
    const float4* pi = reinterpret_cast<const float4*>(xi) + base;
    float4* po_r = reinterpret_cast<float4*>(out) + base;
    float4* po_i = reinterpret_cast<float4*>(out) + (size_t)NPLANE * HW4 + base;

#pragma unroll
    for (int it = 0; it < HALF4 / 256; it++) {       // 8 iters
        const int i = it * 256 + threadIdx.x;
        float4 a = pr[i];                             // plain: use L2-resident tail
        float4 b = pi[i];
        float4 r, m;
        r.x = fmaf(a.x, gr, -b.x * gi);
        r.y = fmaf(a.y, gr, -b.y * gi);
        r.z = fmaf(a.z, gr, -b.z * gi);
        r.w = fmaf(a.w, gr, -b.w * gi);
        m.x = fmaf(a.x, gi, b.x * gr);
        m.y = fmaf(a.y, gi, b.y * gr);
        m.z = fmaf(a.z, gi, b.z * gr);
        m.w = fmaf(a.w, gi, b.w * gr);
        __stcs(po_r + i, r);                          // evict-first writes
        __stcs(po_i + i, m);
    }
}

extern "C" void kernel_launch(void* const* d_in, const int* in_sizes, int n_in,
                              void* d_out, int out_size) {
    const float* xr  = (const float*)d_in[0];
    const float* xi  = (const float*)d_in[1];
    const float* w1r = (const float*)d_in[2];
    const float* w1i = (const float*)d_in[3];
    const float* b1r = (const float*)d_in[4];
    const float* b1i = (const float*)d_in[5];
    const float* w2r = (const float*)d_in[6];
    const float* w2i = (const float*)d_in[7];
    const float* b2r = (const float*)d_in[8];
    const float* b2i = (const float*)d_in[9];
    float* out = (float*)d_out;

    reset_kernel<<<1, 32>>>();
    pool_gate_kernel<<<NHALF, 256>>>(xr, xi,
                                     w1r, w1i, b1r, b1i,
                                     w2r, w2i, b2r, b2i);
    apply_kernel<<<NHALF, 256>>>(xr, xi, out);
}